// round 1
// baseline (speedup 1.0000x reference)
#include <cuda_runtime.h>
#include <cuda_bf16.h>
#include <cstdint>

// ROI Align (masked), two-pass:
//   Pass 1: NCHW -> NHWC transpose into device scratch (coalesced both sides)
//   Pass 2: per-(roi, channel-chunk) gather, coalesced loads over channels,
//           smem-staged so output writes are fully contiguous.

#define N_B   4
#define C_CH  256
#define H_IN  200
#define W_IN  200
#define HW    (H_IN * W_IN)          // 40000
#define K_ROI 512
#define OUT_H 7
#define OUT_W 7
#define BINS  (OUT_H * OUT_W)        // 49
#define SCALE 0.25f

// 4*200*200*256 floats = 163.84 MB scratch (allowed: __device__ global)
__device__ float g_nhwc[(size_t)N_B * HW * C_CH];

// ---------------------------------------------------------------------------
// Pass 1: per-batch transpose of (C, HW) -> (HW, C), 32x32 smem tiles.
// HW = 40000 = 1250*32 exact, C = 256 = 8*32 exact -> no bounds checks.
// ---------------------------------------------------------------------------
__global__ void nchw_to_nhwc(const float* __restrict__ src) {
    __shared__ float tile[32][33];
    const int n  = blockIdx.z;
    const int pT = blockIdx.x * 32;   // position tile (along HW)
    const int cT = blockIdx.y * 32;   // channel tile
    const int tx = threadIdx.x;       // 0..31
    const int ty = threadIdx.y;       // 0..7

    const float* s = src    + (size_t)n * C_CH * HW;
    float*       d = g_nhwc + (size_t)n * HW * C_CH;

#pragma unroll
    for (int j = 0; j < 32; j += 8)
        tile[ty + j][tx] = s[(size_t)(cT + ty + j) * HW + (pT + tx)];

    __syncthreads();

#pragma unroll
    for (int j = 0; j < 32; j += 8)
        d[(size_t)(pT + ty + j) * C_CH + (cT + tx)] = tile[tx][ty + j];
}

// ---------------------------------------------------------------------------
// Pass 2: gather. Grid = (K, C_CH/CH_CHUNK). Block = 256 threads.
// Bin table (offsets + mask-folded bilinear weights) computed by threads 0..48.
// Loads: consecutive threads -> consecutive channels -> 256B coalesced/corner.
// smem staging [c][bin] (stride 49, odd -> conflict-free), then contiguous
// writes to out[k, c0:c0+CH, :, :].
// ---------------------------------------------------------------------------
#define CH_CHUNK 64

__global__ void roi_gather(const float* __restrict__ rois,
                           const float* __restrict__ masks,
                           float* __restrict__ out) {
    __shared__ float sbuf[CH_CHUNK * BINS];   // 12544 B
    __shared__ int   soff[BINS][4];
    __shared__ float swgt[BINS][4];
    __shared__ int   sbase;

    const int k  = blockIdx.x;
    const int c0 = blockIdx.y * CH_CHUNK;
    const int t  = threadIdx.x;

    if (t < BINS) {
        const float bb  = rois[k * 5 + 0];
        const float fx1 = rois[k * 5 + 1] * SCALE;
        const float fy1 = rois[k * 5 + 2] * SCALE;
        const float fx2 = rois[k * 5 + 3] * SCALE;
        const float fy2 = rois[k * 5 + 4] * SCALE;
        const float rw  = fmaxf(fx2 - fx1, 1.0f);
        const float rh  = fmaxf(fy2 - fy1, 1.0f);
        const float bw  = rw * (1.0f / OUT_W);
        const float bh  = rh * (1.0f / OUT_H);

        const int oh = t / OUT_W;
        const int ow = t % OUT_W;

        const float ys  = fy1 + ((float)oh + 0.5f) * bh;
        const float xs  = fx1 + ((float)ow + 0.5f) * bw;
        const float y0f = floorf(ys);
        const float x0f = floorf(xs);
        const float ly  = ys - y0f;
        const float lx  = xs - x0f;

        int y0  = min(max((int)y0f, 0), H_IN - 1);
        int y1i = min(y0 + 1, H_IN - 1);
        int x0  = min(max((int)x0f, 0), W_IN - 1);
        int x1i = min(x0 + 1, W_IN - 1);

        const float m = masks[k * BINS + t];
        swgt[t][0] = (1.0f - ly) * (1.0f - lx) * m;
        swgt[t][1] = (1.0f - ly) * lx * m;
        swgt[t][2] = ly * (1.0f - lx) * m;
        swgt[t][3] = ly * lx * m;
        soff[t][0] = (y0  * W_IN + x0 ) * C_CH;
        soff[t][1] = (y0  * W_IN + x1i) * C_CH;
        soff[t][2] = (y1i * W_IN + x0 ) * C_CH;
        soff[t][3] = (y1i * W_IN + x1i) * C_CH;
        if (t == 0) sbase = (int)bb * (HW * C_CH);
    }
    __syncthreads();

    const float* base = g_nhwc + (size_t)sbase + c0;

    // compute: index i -> (bin = i/CH, c = i%CH); c fastest -> coalesced loads
#pragma unroll 4
    for (int i = t; i < BINS * CH_CHUNK; i += 256) {
        const int bin = i >> 6;            // CH_CHUNK = 64
        const int c   = i & (CH_CHUNK - 1);
        const float* p = base + c;
        const float v = swgt[bin][0] * p[soff[bin][0]]
                      + swgt[bin][1] * p[soff[bin][1]]
                      + swgt[bin][2] * p[soff[bin][2]]
                      + swgt[bin][3] * p[soff[bin][3]];
        sbuf[c * BINS + bin] = v;          // stride 49: bank-conflict-free
    }
    __syncthreads();

    float* o = out + (size_t)k * (C_CH * BINS) + (size_t)c0 * BINS;
#pragma unroll 4
    for (int i = t; i < BINS * CH_CHUNK; i += 256)
        o[i] = sbuf[i];
}

extern "C" void kernel_launch(void* const* d_in, const int* in_sizes, int n_in,
                              void* d_out, int out_size) {
    const float* inputs = (const float*)d_in[0];  // [4,256,200,200]
    const float* rois   = (const float*)d_in[1];  // [512,5]
    const float* masks  = (const float*)d_in[2];  // [512,7,7]
    float* out = (float*)d_out;                   // [512,256,7,7]

    (void)in_sizes; (void)n_in; (void)out_size;

    dim3 tgrid(HW / 32, C_CH / 32, N_B);          // 1250 x 8 x 4
    dim3 tblk(32, 8);
    nchw_to_nhwc<<<tgrid, tblk>>>(inputs);

    dim3 ggrid(K_ROI, C_CH / CH_CHUNK);           // 512 x 4
    roi_gather<<<ggrid, 256>>>(rois, masks, out);
}